// round 6
// baseline (speedup 1.0000x reference)
#include <cuda_runtime.h>

// ---------------- problem constants ---------------------------------------
#define Hdim   128
#define Odim   32
#define INdim  64
#define RB     8           // init kernel rows per block
#define RB2    16          // node/combine rows per block
#define NTHR   128
#define NTHR2  384         // 3 warpgroups (one per gate)
#define MAXB   16384
#define MAXLVL 6

// ---------------- static device scratch -----------------------------------
__device__ float g_H0 [(size_t)MAXB * Hdim];
__device__ float g_HAI[(size_t)MAXLVL * MAXB * Hdim];
__device__ float g_H2 [(size_t)MAXLVL * MAXB * Hdim];
__device__ float g_PR [(size_t)(MAXLVL + 1) * MAXB * Odim];

// packed weights: [gate][k4][j][4] per matrix
#define OFF_WH_A 0
#define OFF_WI_A 49152
#define OFF_WH_F 61440
#define OFF_WI_F 110592
#define OFF_UF   122880
#define OFF_UA   139264
__device__ float g_WP[155648];

typedef unsigned long long u64;
union F4U { float4 f; ulonglong2 u; };

__device__ __forceinline__ void ffma2(u64& d, u64 a, u64 b) {
    asm volatile("fma.rn.f32x2 %0, %1, %2, %0;" : "+l"(d) : "l"(a), "l"(b));
}
__device__ __forceinline__ u64 pack2(float lo, float hi) {
    u64 r; asm("mov.b64 %0, {%1, %2};" : "=l"(r) : "f"(lo), "f"(hi)); return r;
}
__device__ __forceinline__ float f2sum(u64 v) {
    float lo, hi; asm("mov.b64 {%0, %1}, %2;" : "=f"(lo), "=f"(hi) : "l"(v));
    return lo + hi;
}
__device__ __forceinline__ float sigmoidf_(float x) {
    return 1.0f / (1.0f + expf(-x));
}

// ---------------- weight repack prologue ----------------------------------
__device__ __forceinline__ void pack_one(const float* __restrict__ src,
                                         float* __restrict__ dst, int g) {
    int k4 = g >> 7, j = g & 127;
    float4 v;
    v.x = src[(size_t)(4 * k4 + 0) * 128 + j];
    v.y = src[(size_t)(4 * k4 + 1) * 128 + j];
    v.z = src[(size_t)(4 * k4 + 2) * 128 + j];
    v.w = src[(size_t)(4 * k4 + 3) * 128 + j];
    *reinterpret_cast<float4*>(dst + (size_t)g * 4) = v;
}

__global__ void pack_kernel(const float* __restrict__ awh, const float* __restrict__ awi,
                            const float* __restrict__ fwh, const float* __restrict__ fwi,
                            const float* __restrict__ ufw, const float* __restrict__ uaw,
                            float* __restrict__ WP) {
    int g = blockIdx.x * blockDim.x + threadIdx.x;
    if      (g < 12288) pack_one(awh, WP + OFF_WH_A, g);
    else if (g < 15360) pack_one(awi, WP + OFF_WI_A, g - 12288);
    else if (g < 27648) pack_one(fwh, WP + OFF_WH_F, g - 15360);
    else if (g < 30720) pack_one(fwi, WP + OFF_WI_F, g - 27648);
    else if (g < 34816) pack_one(ufw, WP + OFF_UF,   g - 30720);
    else if (g < 38912) pack_one(uaw, WP + OFF_UA,   g - 34816);
}

// ---------------- init: hidden = z @ z2h_w + z2h_b ------------------------
__global__ void __launch_bounds__(NTHR)
init_kernel(const float* __restrict__ z, const float* __restrict__ w,
            const float* __restrict__ b, float* __restrict__ hout) {
    __shared__ float zs[RB][INdim];
    const int j    = threadIdx.x;
    const int row0 = blockIdx.x * RB;

    {
        const float4* src = reinterpret_cast<const float4*>(z + (size_t)row0 * INdim);
        float4* dst = reinterpret_cast<float4*>(&zs[0][0]);
        for (int i = j; i < RB * INdim / 4; i += NTHR) dst[i] = src[i];
    }
    __syncthreads();

    const float bb = b[j];
    float acc[RB];
#pragma unroll
    for (int i = 0; i < RB; i++) acc[i] = bb;
#pragma unroll 4
    for (int k = 0; k < INdim; k += 4) {
        float4 hv[RB];
#pragma unroll
        for (int i = 0; i < RB; i++)
            hv[i] = *reinterpret_cast<const float4*>(&zs[i][k]);
#pragma unroll
        for (int kk = 0; kk < 4; kk++) {
            float wv = w[(size_t)(k + kk) * Hdim + j];
#pragma unroll
            for (int i = 0; i < RB; i++) {
                float h = (kk == 0) ? hv[i].x : (kk == 1) ? hv[i].y
                          : (kk == 2) ? hv[i].z : hv[i].w;
                acc[i] += h * wv;
            }
        }
    }
#pragma unroll
    for (int i = 0; i < RB; i++)
        hout[(size_t)(row0 + i) * Hdim + j] = acc[i];
}

// ---------------- shared accumulation core ---------------------------------
// acc[16] over nk4 k-groups; pact row stride in ulonglong2 units; 8-row halves
// bound register pressure (weights reused across both halves).
__device__ __forceinline__ void accum_k(u64* acc, const float4* __restrict__ pw,
                                        int nk4, const ulonglong2* __restrict__ pact,
                                        int rowStride) {
#pragma unroll 4
    for (int k4 = 0; k4 < nk4; k4++) {
        F4U w; w.f = pw[k4 * 128];
#pragma unroll
        for (int half = 0; half < 2; half++) {
            ulonglong2 a[8];
#pragma unroll
            for (int i = 0; i < 8; i++)
                a[i] = pact[(half * 8 + i) * rowStride + k4];
#pragma unroll
            for (int i = 0; i < 8; i++) {
                ffma2(acc[half * 8 + i], a[i].x, w.u.x);
                ffma2(acc[half * 8 + i], a[i].y, w.u.y);
            }
        }
    }
}

// ---------------- fused node kernel (gate-split warpgroups) ----------------
__global__ void __launch_bounds__(NTHR2, 2)
node_kernel(const float* __restrict__ h_a,
            const float* __restrict__ h2o_w, const float* __restrict__ h2o_b,
            const float* __restrict__ wiP,   const float* __restrict__ bi,
            const float* __restrict__ whP,   const float* __restrict__ bh,
            float* __restrict__ pred_out, float* __restrict__ probs_out,
            float* __restrict__ h_out) {
    __shared__ float hs[RB2 * Hdim];
    __shared__ float ps[RB2 * Odim];
    __shared__ float gR[RB2 * Hdim];
    __shared__ float gZ[RB2 * Hdim];
    __shared__ float xn[RB2 * Hdim];
    const int t    = threadIdx.x;
    const int row0 = blockIdx.x * RB2;

    {
        const float4* src = reinterpret_cast<const float4*>(h_a + (size_t)row0 * Hdim);
        float4* dst = reinterpret_cast<float4*>(hs);
        for (int i = t; i < RB2 * Hdim / 4; i += NTHR2) dst[i] = src[i];
    }
    __syncthreads();

    // ---- pred + softmax: warps 0..7, warp w -> rows 2w, 2w+1; lane = o ----
    {
        const int o = t & 31, w = t >> 5;
        if (w < 8) {
            float acc[2];
            const float bb = h2o_b[o];
            acc[0] = bb; acc[1] = bb;
#pragma unroll 4
            for (int k = 0; k < Hdim; k += 4) {
                float4 h0 = *reinterpret_cast<const float4*>(&hs[(w * 2 + 0) * Hdim + k]);
                float4 h1 = *reinterpret_cast<const float4*>(&hs[(w * 2 + 1) * Hdim + k]);
#pragma unroll
                for (int kk = 0; kk < 4; kk++) {
                    float wv = h2o_w[(size_t)(k + kk) * Odim + o];
                    float a0 = (kk == 0) ? h0.x : (kk == 1) ? h0.y : (kk == 2) ? h0.z : h0.w;
                    float a1 = (kk == 0) ? h1.x : (kk == 1) ? h1.y : (kk == 2) ? h1.z : h1.w;
                    acc[0] += a0 * wv;
                    acc[1] += a1 * wv;
                }
            }
#pragma unroll
            for (int i = 0; i < 2; i++) {
                int r = w * 2 + i;
                float v = acc[i];
                pred_out[(size_t)(row0 + r) * Odim + o] = v;
                float m = v;
#pragma unroll
                for (int s = 16; s > 0; s >>= 1)
                    m = fmaxf(m, __shfl_xor_sync(0xffffffffu, m, s));
                float e = expf(v - m);
                float ssum = e;
#pragma unroll
                for (int s = 16; s > 0; s >>= 1)
                    ssum += __shfl_xor_sync(0xffffffffu, ssum, s);
                float p = e / ssum;
                ps[r * Odim + o] = p;
                probs_out[(size_t)(row0 + r) * Odim + o] = p;
            }
        }
    }
    __syncthreads();

    // ---- gate accumulation: warpgroup g owns gate g ----
    const int j = t & 127, g = t >> 7;
    const float4* pw  = reinterpret_cast<const float4*>(whP) + g * 4096 + j;
    const float4* pwi = reinterpret_cast<const float4*>(wiP) + g * 1024 + j;
    const ulonglong2* ph = reinterpret_cast<const ulonglong2*>(hs);  // stride 32
    const ulonglong2* pp = reinterpret_cast<const ulonglong2*>(ps);  // stride 8

    u64 acc[RB2];
    if (g < 2) {
        const float b0 = bi[g * Hdim + j] + bh[g * Hdim + j];
#pragma unroll
        for (int i = 0; i < RB2; i++) acc[i] = pack2(b0, 0.0f);
        accum_k(acc, pwi, Odim / 4, pp, 8);
        accum_k(acc, pw,  Hdim / 4, ph, 32);
        float* dstg = (g == 0) ? gR : gZ;
#pragma unroll
        for (int i = 0; i < RB2; i++)
            dstg[i * Hdim + j] = sigmoidf_(f2sum(acc[i]));
    } else {
        const float bx = bi[2 * Hdim + j];
#pragma unroll
        for (int i = 0; i < RB2; i++) acc[i] = pack2(bx, 0.0f);
        accum_k(acc, pwi, Odim / 4, pp, 8);
#pragma unroll
        for (int i = 0; i < RB2; i++)
            xn[i * Hdim + j] = f2sum(acc[i]);
        const float bh2 = bh[2 * Hdim + j];
#pragma unroll
        for (int i = 0; i < RB2; i++) acc[i] = pack2(bh2, 0.0f);
        accum_k(acc, pw, Hdim / 4, ph, 32);
    }
    __syncthreads();

    if (g == 2) {
        float* po = h_out + (size_t)row0 * Hdim + j;
#pragma unroll
        for (int i = 0; i < RB2; i++) {
            float rg = gR[i * Hdim + j];
            float zg = gZ[i * Hdim + j];
            float n  = tanhf(xn[i * Hdim + j] + rg * f2sum(acc[i]));
            float hv = hs[i * Hdim + j];
            po[i * Hdim] = (1.0f - zg) * n + zg * hv;
        }
    }
}

// ---------------- fused combine kernel (gate-split + merge) ----------------
__global__ void __launch_bounds__(NTHR2, 2)
combine_kernel(const float* __restrict__ probs_fc,
               const float* __restrict__ h_ai, const float* __restrict__ h_a,
               const float* __restrict__ wiP,  const float* __restrict__ bi,
               const float* __restrict__ whP,  const float* __restrict__ bh,
               const float* __restrict__ ufP,  const float* __restrict__ ufb,
               const float* __restrict__ uaP,  const float* __restrict__ uab,
               float* __restrict__ h2_out) {
    __shared__ float hs[RB2 * Hdim];   // h_ai, later h_a
    __shared__ float ps[RB2 * Odim];
    __shared__ float gR[RB2 * Hdim];
    __shared__ float gZ[RB2 * Hdim];
    __shared__ float xn[RB2 * Hdim];
    __shared__ float hf[RB2 * Hdim];
    const int t    = threadIdx.x;
    const int row0 = blockIdx.x * RB2;

    {
        const float4* src = reinterpret_cast<const float4*>(h_ai + (size_t)row0 * Hdim);
        float4* dst = reinterpret_cast<float4*>(hs);
        for (int i = t; i < RB2 * Hdim / 4; i += NTHR2) dst[i] = src[i];
        const float4* psrc = reinterpret_cast<const float4*>(probs_fc + (size_t)row0 * Odim);
        float4* pdst = reinterpret_cast<float4*>(ps);
        if (t < RB2 * Odim / 4) pdst[t] = psrc[t];
    }
    __syncthreads();

    const int j = t & 127, g = t >> 7;
    const float4* pw  = reinterpret_cast<const float4*>(whP) + g * 4096 + j;
    const float4* pwi = reinterpret_cast<const float4*>(wiP) + g * 1024 + j;
    const ulonglong2* ph = reinterpret_cast<const ulonglong2*>(hs);
    const ulonglong2* pp = reinterpret_cast<const ulonglong2*>(ps);

    u64 acc[RB2];
    if (g < 2) {
        const float b0 = bi[g * Hdim + j] + bh[g * Hdim + j];
#pragma unroll
        for (int i = 0; i < RB2; i++) acc[i] = pack2(b0, 0.0f);
        accum_k(acc, pwi, Odim / 4, pp, 8);
        accum_k(acc, pw,  Hdim / 4, ph, 32);
        float* dstg = (g == 0) ? gR : gZ;
#pragma unroll
        for (int i = 0; i < RB2; i++)
            dstg[i * Hdim + j] = sigmoidf_(f2sum(acc[i]));
    } else {
        const float bx = bi[2 * Hdim + j];
#pragma unroll
        for (int i = 0; i < RB2; i++) acc[i] = pack2(bx, 0.0f);
        accum_k(acc, pwi, Odim / 4, pp, 8);
#pragma unroll
        for (int i = 0; i < RB2; i++)
            xn[i * Hdim + j] = f2sum(acc[i]);
        const float bh2 = bh[2 * Hdim + j];
#pragma unroll
        for (int i = 0; i < RB2; i++) acc[i] = pack2(bh2, 0.0f);
        accum_k(acc, pw, Hdim / 4, ph, 32);
    }
    __syncthreads();

    if (g == 2) {
#pragma unroll
        for (int i = 0; i < RB2; i++) {
            float rg = gR[i * Hdim + j];
            float zg = gZ[i * Hdim + j];
            float n  = tanhf(xn[i * Hdim + j] + rg * f2sum(acc[i]));
            float hv = hs[i * Hdim + j];
            hf[i * Hdim + j] = (1.0f - zg) * n + zg * hv;
        }
    }
    __syncthreads();
    // reload hs with h_a
    {
        const float4* src = reinterpret_cast<const float4*>(h_a + (size_t)row0 * Hdim);
        float4* dst = reinterpret_cast<float4*>(hs);
        for (int i = t; i < RB2 * Hdim / 4; i += NTHR2) dst[i] = src[i];
    }
    __syncthreads();

    // merge: h2 = tanh(hf@ufw + hs@uaw + ufb + uab); warpgroup g -> row slice
    {
        const int r0 = g * 6;
        const int nr = (g < 2) ? 6 : 4;              // rows 0-5 / 6-11 / 12-15
        const float bb = ufb[j] + uab[j];
        u64 macc[6];
#pragma unroll
        for (int i = 0; i < 6; i++) macc[i] = pack2(bb, 0.0f);

        const float4* pf = reinterpret_cast<const float4*>(ufP) + j;
        const float4* pa = reinterpret_cast<const float4*>(uaP) + j;
        const ulonglong2* phf = reinterpret_cast<const ulonglong2*>(hf);
        const ulonglong2* phs = reinterpret_cast<const ulonglong2*>(hs);
#pragma unroll 4
        for (int k4 = 0; k4 < Hdim / 4; k4++) {
            F4U wf, wa;
            wf.f = pf[k4 * 128];
            wa.f = pa[k4 * 128];
#pragma unroll
            for (int i = 0; i < 6; i++) {
                if (i < nr) {
                    ulonglong2 hv = phf[(r0 + i) * 32 + k4];
                    ulonglong2 av = phs[(r0 + i) * 32 + k4];
                    ffma2(macc[i], hv.x, wf.u.x); ffma2(macc[i], hv.y, wf.u.y);
                    ffma2(macc[i], av.x, wa.u.x); ffma2(macc[i], av.y, wa.u.y);
                }
            }
        }
        float* po = h2_out + (size_t)(row0 + r0) * Hdim + j;
#pragma unroll
        for (int i = 0; i < 6; i++)
            if (i < nr) po[i * Hdim] = tanhf(f2sum(macc[i]));
    }
}

// ---------------- host-side tree orchestration (single stream) ------------
struct EmitCtx {
    const float *h2o_w, *h2o_b;
    const float *abi, *abh, *fbi, *fbh;
    const float *uab, *ufb;
    const float *awiP, *awhP, *fwiP, *fwhP, *ufP, *uaP;
    float* out;
    float *HAI, *H2, *PR;
    int B, grid, idx;
};

static void emit_node(EmitCtx& P, int lvl, int d, const float* h_in) {
    float* probs = P.PR  + (size_t)lvl * P.B * Odim;
    float* h_ai  = P.HAI + (size_t)lvl * P.B * Hdim;
    node_kernel<<<P.grid, NTHR2>>>(h_in, P.h2o_w, P.h2o_b,
                                   P.awiP, P.abi, P.awhP, P.abh,
                                   P.out + (size_t)P.idx * P.B * Odim,
                                   probs, h_ai);
    P.idx++;
    if (d > 0) {
        emit_node(P, lvl + 1, d - 1, h_ai);
        float* h2 = P.H2 + (size_t)lvl * P.B * Hdim;
        combine_kernel<<<P.grid, NTHR2>>>(P.PR + (size_t)(lvl + 1) * P.B * Odim,
                                          h_ai, h_in,
                                          P.fwiP, P.fbi, P.fwhP, P.fbh,
                                          P.ufP, P.ufb, P.uaP, P.uab, h2);
        emit_node(P, lvl + 1, d - 1, h2);
    }
}

extern "C" void kernel_launch(void* const* d_in, const int* in_sizes, int n_in,
                              void* d_out, int out_size) {
    const float* z      = (const float*)d_in[0];
    const float* z2h_w  = (const float*)d_in[1];
    const float* z2h_b  = (const float*)d_in[2];
    const float* h2o_w  = (const float*)d_in[3];
    const float* h2o_b  = (const float*)d_in[4];
    const float* awi    = (const float*)d_in[5];
    const float* abi    = (const float*)d_in[6];
    const float* awh    = (const float*)d_in[7];
    const float* abh    = (const float*)d_in[8];
    const float* fwi    = (const float*)d_in[9];
    const float* fbi    = (const float*)d_in[10];
    const float* fwh    = (const float*)d_in[11];
    const float* fbh    = (const float*)d_in[12];
    const float* uaw    = (const float*)d_in[13];
    const float* uab    = (const float*)d_in[14];
    const float* ufw    = (const float*)d_in[15];
    const float* ufb    = (const float*)d_in[16];

    const int H  = in_sizes[2];               // 128
    const int O  = in_sizes[4];               // 32
    const int IN = in_sizes[1] / H;           // 64
    const int B  = in_sizes[0] / IN;          // 16384
    const int nn = out_size / (B * O);        // tree nodes (31)
    int depth = 0;
    while (((2 << depth) - 1) < nn) depth++;

    float *H0p, *HAIp, *H2p, *PRp, *WPp;
    cudaGetSymbolAddress((void**)&H0p,  g_H0);
    cudaGetSymbolAddress((void**)&HAIp, g_HAI);
    cudaGetSymbolAddress((void**)&H2p,  g_H2);
    cudaGetSymbolAddress((void**)&PRp,  g_PR);
    cudaGetSymbolAddress((void**)&WPp,  g_WP);

    pack_kernel<<<(38912 + 255) / 256, 256>>>(awh, awi, fwh, fwi, ufw, uaw, WPp);
    init_kernel<<<B / RB, NTHR>>>(z, z2h_w, z2h_b, H0p);

    EmitCtx P;
    P.h2o_w = h2o_w; P.h2o_b = h2o_b;
    P.abi = abi; P.abh = abh; P.fbi = fbi; P.fbh = fbh;
    P.uab = uab; P.ufb = ufb;
    P.awiP = WPp + OFF_WI_A; P.awhP = WPp + OFF_WH_A;
    P.fwiP = WPp + OFF_WI_F; P.fwhP = WPp + OFF_WH_F;
    P.ufP  = WPp + OFF_UF;   P.uaP  = WPp + OFF_UA;
    P.out  = (float*)d_out;
    P.HAI = HAIp; P.H2 = H2p; P.PR = PRp;
    P.B = B; P.grid = B / RB2; P.idx = 0;

    emit_node(P, 0, depth, H0p);
}